// round 10
// baseline (speedup 1.0000x reference)
#include <cuda_runtime.h>
#include <cuda_fp16.h>

// CapsNet dynamic routing — fused; lane-pair (n,h) mapping, b0 priors fully
// register-resident, b1 via one interleaved SMEM plane. 2 CTAs/SM.
// x:  [B=256, N=1152, Ci=8]  fp32
// W:  [C=10, N=1152, Ci=8, Co=16] fp32
// out:[C, B, Co] fp32
//
// Prep: W -> fp16, uint4 index ((c*36+g32)*8+i)*64 + nl*2 + h
//   (n = g32*32+nl, co = 8h+j) -> warp W load = one contiguous 512B txn
//   with lane = 2*(n-n0)+h.
// Main: 384 threads (12 warps), BT=2, launch_bounds(384,2). Thread slot =
// (n, h): computes u[n][8h..8h+8) for both b. x: each thread LDGs its 16B
// half-row; partner half via shfl_xor 1. Routing: 6 slots/thread, butterfly
// reductions over same-h lanes, logits via partner shfl, no-max softmax.

static constexpr int kB  = 256;
static constexpr int kN  = 1152;
static constexpr int kCi = 8;
static constexpr int kC  = 10;
static constexpr int kCo = 16;
static constexpr int kBT = 2;
static constexpr int kThreads = 384;   // 12 warps
static constexpr int kWarps = 12;
static constexpr int kSlots = 6;       // (n,h) slots per thread: 2304/384

static constexpr int kWTotal = kC * kN * kCi * kCo;   // halfs

__device__ __half g_Wt[kWTotal];

struct Smem {
    uint4 u1[kN * 2];           // b1 fp16 priors, interleaved: [n*2+h] -> 8 halfs
    float red[kWarps][kCo];
    float zsc[kWarps];
    float vv[kCo];
};

// ---------------- packed f32x2 helpers --------------------------------------
__device__ __forceinline__ unsigned long long pk2(float a, float b) {
    unsigned long long r;
    asm("mov.b64 %0, {%1, %2};" : "=l"(r) : "f"(a), "f"(b));
    return r;
}
__device__ __forceinline__ unsigned long long fma2(unsigned long long a,
                                                   unsigned long long b,
                                                   unsigned long long c) {
    unsigned long long d;
    asm("fma.rn.f32x2 %0, %1, %2, %3;" : "=l"(d) : "l"(a), "l"(b), "l"(c));
    return d;
}
__device__ __forceinline__ float2 upk2(unsigned long long a) {
    float x, y;
    asm("mov.b64 {%0, %1}, %2;" : "=f"(x), "=f"(y) : "l"(a));
    return make_float2(x, y);
}

// ---------------- prep: coalesced SMEM-transpose + fp16 convert -------------
__global__ __launch_bounds__(256)
void transpose_W_kernel(const float* __restrict__ W) {
    __shared__ __half s[32][136];          // 128 halfs/row + 8 pad
    const int blk = blockIdx.x;            // c*36 + g32
    const int tid = threadIdx.x;

    const float4* src = reinterpret_cast<const float4*>(W) + (size_t)blk * 1024;
    #pragma unroll
    for (int q = 0; q < 4; ++q) {
        const int v  = tid + q * 256;
        float4 f = src[v];
        const int nl  = v >> 5;
        const int col = (v & 31) * 4;
        *reinterpret_cast<__half2*>(&s[nl][col])     = __floats2half2_rn(f.x, f.y);
        *reinterpret_cast<__half2*>(&s[nl][col + 2]) = __floats2half2_rn(f.z, f.w);
    }
    __syncthreads();

    uint4* dst = reinterpret_cast<uint4*>(g_Wt) + (size_t)blk * 512;
    #pragma unroll
    for (int q = 0; q < 2; ++q) {
        const int o  = tid + q * 256;      // output idx = i*64 + nl*2 + h
        const int h  = o & 1;
        const int nl = (o >> 1) & 31;
        const int i  = o >> 6;
        dst[o] = *reinterpret_cast<const uint4*>(&s[nl][(i * 2 + h) * 8]);
    }
}

// ---------------- helpers ----------------------------------------------------
// Butterfly reduce of 8 values over the 16 same-h lanes (offsets 2,4,8 + 16).
// On exit lane l holds total for m = ((l>>1)&1)*4 + ((l>>2)&1)*2 + ((l>>3)&1).
__device__ __forceinline__ float warp_reduce8(float a[8], int lane) {
    #pragma unroll
    for (int s = 0; s < 3; ++s) {
        const int off = 2 << s;
        const bool hi = (lane >> (s + 1)) & 1;
        const int hh = 4 >> s;               // 4,2,1
        #pragma unroll
        for (int i = 0; i < hh; ++i) {
            float send = hi ? a[i] : a[i + hh];
            float recv = __shfl_xor_sync(0xFFFFFFFFu, send, off);
            a[i] = (hi ? a[i + hh] : a[i]) + recv;
        }
    }
    return a[0] + __shfl_xor_sync(0xFFFFFFFFu, a[0], 16);
}

// Routing for one b on register-resident packed u (6 slots x 4 half2 = own oct).
__device__ __forceinline__ void route_one(
    Smem& sm, const __half2 u2[kSlots][4],
    int tid, int lane, int wrp, int h, int coOwn,
    float* __restrict__ outp)
{
    float lg[kSlots];

    // ---- iteration 0: uniform probs ----
    {
        float r[8];
        #pragma unroll
        for (int q = 0; q < 4; ++q) {
            float sx = 0.f, sy = 0.f;
            #pragma unroll
            for (int k = 0; k < kSlots; ++k) {
                float2 f = __half22float2(u2[k][q]);
                sx += f.x; sy += f.y;
            }
            r[2*q] = sx; r[2*q+1] = sy;
        }
        float tot = warp_reduce8(r, lane);
        if (lane < 16) sm.red[wrp][coOwn] = tot;
        __syncthreads();

        if (tid < kCo) {
            float s = 0.f;
            #pragma unroll
            for (int w = 0; w < kWarps; ++w) s += sm.red[w][tid];
            s *= (1.0f / kN);
            float sq = s * s;
            #pragma unroll
            for (int off = 8; off; off >>= 1)
                sq += __shfl_xor_sync(0x0000FFFFu, sq, off);
            sm.vv[tid] = s * sqrtf(sq) / (1.0f + sq);
        }
        __syncthreads();

        float v[8];
        #pragma unroll
        for (int j = 0; j < 8; ++j) v[j] = sm.vv[h * 8 + j];
        #pragma unroll
        for (int k = 0; k < kSlots; ++k) {
            float d = 0.f;
            #pragma unroll
            for (int q = 0; q < 4; ++q) {
                float2 f = __half22float2(u2[k][q]);
                d += f.x * v[2*q] + f.y * v[2*q+1];
            }
            lg[k] = d + __shfl_xor_sync(0xFFFFFFFFu, d, 1);
        }
    }

    // ---- iterations 1, 2 (no-max softmax: |logits| << 88) ----
    #pragma unroll 1
    for (int it = 1; it < 3; ++it) {
        float e[kSlots];
        float zp = 0.f;
        #pragma unroll
        for (int k = 0; k < kSlots; ++k) {
            e[k] = __expf(lg[k]);
            zp += e[k];
        }
        if (h) zp = 0.f;                     // h-pairs duplicate logits
        #pragma unroll
        for (int off = 16; off; off >>= 1)
            zp += __shfl_xor_sync(0xFFFFFFFFu, zp, off);

        float r[8];
        #pragma unroll
        for (int q = 0; q < 4; ++q) {
            float sx = 0.f, sy = 0.f;
            #pragma unroll
            for (int k = 0; k < kSlots; ++k) {
                float2 f = __half22float2(u2[k][q]);
                sx += e[k] * f.x; sy += e[k] * f.y;
            }
            r[2*q] = sx; r[2*q+1] = sy;
        }
        float tot = warp_reduce8(r, lane);
        if (lane == 0) sm.zsc[wrp] = zp;
        if (lane < 16) sm.red[wrp][coOwn] = tot;
        __syncthreads();

        if (tid < kCo) {
            float Z = 0.f, s = 0.f;
            #pragma unroll
            for (int w = 0; w < kWarps; ++w) { Z += sm.zsc[w]; s += sm.red[w][tid]; }
            s = __fdividef(s, Z);
            float sq = s * s;
            #pragma unroll
            for (int off = 8; off; off >>= 1)
                sq += __shfl_xor_sync(0x0000FFFFu, sq, off);
            float v = s * sqrtf(sq) / (1.0f + sq);
            sm.vv[tid] = v;
            if (it == 2)
                outp[tid] = v;
        }
        __syncthreads();

        if (it == 1) {
            float v[8];
            #pragma unroll
            for (int j = 0; j < 8; ++j) v[j] = sm.vv[h * 8 + j];
            #pragma unroll
            for (int k = 0; k < kSlots; ++k) {
                float d = 0.f;
                #pragma unroll
                for (int q = 0; q < 4; ++q) {
                    float2 f = __half22float2(u2[k][q]);
                    d += f.x * v[2*q] + f.y * v[2*q+1];
                }
                lg[k] += d + __shfl_xor_sync(0xFFFFFFFFu, d, 1);
            }
        }
    }
}

// ---------------- main --------------------------------------------------------
__global__ __launch_bounds__(kThreads, 2)
void caps_routing_kernel(const float* __restrict__ x,
                         float* __restrict__ out)
{
    extern __shared__ unsigned char smem_u8[];
    Smem& sm = *reinterpret_cast<Smem*>(smem_u8);

    const int tid  = threadIdx.x;
    const int lane = tid & 31;
    const int wrp  = tid >> 5;           // 0..11
    const int h    = lane & 1;           // co-oct
    const int c    = blockIdx.y;
    const int b0   = blockIdx.x * kBT;
    // co this lane owns after warp_reduce8
    const int coOwn = h * 8 + ((lane >> 1) & 1) * 4 + ((lane >> 2) & 1) * 2
                    + ((lane >> 3) & 1);

    __half2 u2[kSlots][4];               // b0 priors, own co-oct, registers

    // ---------------- Phase 1: priors (lane-pair mapping) -------------------
    {
        const float4* __restrict__ X4  = reinterpret_cast<const float4*>(x);
        const uint4*  __restrict__ Wt4 = reinterpret_cast<const uint4*>(g_Wt);

        #pragma unroll 1
        for (int p = 0; p < kSlots; ++p) {
            const int nbase = p * 192 + wrp * 16;       // warp's 16 rows

            // my 16B half-row per b (contiguous across warp); partner via shfl
            float4 xm0 = X4[b0 * (kN * 2) + nbase * 2 + lane];
            float4 xm1 = X4[(b0 + 1) * (kN * 2) + nbase * 2 + lane];
            float q00 = __shfl_xor_sync(0xFFFFFFFFu, xm0.x, 1);
            float q01 = __shfl_xor_sync(0xFFFFFFFFu, xm0.y, 1);
            float q02 = __shfl_xor_sync(0xFFFFFFFFu, xm0.z, 1);
            float q03 = __shfl_xor_sync(0xFFFFFFFFu, xm0.w, 1);
            float q10 = __shfl_xor_sync(0xFFFFFFFFu, xm1.x, 1);
            float q11 = __shfl_xor_sync(0xFFFFFFFFu, xm1.y, 1);
            float q12 = __shfl_xor_sync(0xFFFFFFFFu, xm1.z, 1);
            float q13 = __shfl_xor_sync(0xFFFFFFFFu, xm1.w, 1);
            float xv0[8], xv1[8];
            xv0[0] = h ? q00 : xm0.x;  xv0[1] = h ? q01 : xm0.y;
            xv0[2] = h ? q02 : xm0.z;  xv0[3] = h ? q03 : xm0.w;
            xv0[4] = h ? xm0.x : q00;  xv0[5] = h ? xm0.y : q01;
            xv0[6] = h ? xm0.z : q02;  xv0[7] = h ? xm0.w : q03;
            xv1[0] = h ? q10 : xm1.x;  xv1[1] = h ? q11 : xm1.y;
            xv1[2] = h ? q12 : xm1.z;  xv1[3] = h ? q13 : xm1.w;
            xv1[4] = h ? xm1.x : q10;  xv1[5] = h ? xm1.y : q11;
            xv1[6] = h ? xm1.z : q12;  xv1[7] = h ? xm1.w : q13;

            unsigned long long acc0[4] = {0ull, 0ull, 0ull, 0ull};
            unsigned long long acc1[4] = {0ull, 0ull, 0ull, 0ull};
            // W uint4 idx: ((c*36 + p*6 + wrp/2)*8 + i)*64 + (wrp&1)*32 + lane
            const size_t wb = ((size_t)(c * 36 + p * 6 + (wrp >> 1)) * kCi) * 64
                            + (wrp & 1) * 32 + lane;
            #pragma unroll
            for (int i = 0; i < kCi; ++i) {
                uint4 w = Wt4[wb + (size_t)i * 64];
                const __half2* hp = reinterpret_cast<const __half2*>(&w);
                const unsigned long long xi0 = pk2(xv0[i], xv0[i]);
                const unsigned long long xi1 = pk2(xv1[i], xv1[i]);
                #pragma unroll
                for (int q = 0; q < 4; ++q) {
                    float2 f = __half22float2(hp[q]);
                    unsigned long long wp = pk2(f.x, f.y);
                    acc0[q] = fma2(xi0, wp, acc0[q]);
                    acc1[q] = fma2(xi1, wp, acc1[q]);
                }
            }
            __half2 p1[4];
            #pragma unroll
            for (int q = 0; q < 4; ++q) {
                float2 f0 = upk2(acc0[q]);
                float2 f1 = upk2(acc1[q]);
                u2[p][q] = __floats2half2_rn(f0.x, f0.y);   // b0 stays in regs
                p1[q]    = __floats2half2_rn(f1.x, f1.y);
            }
            sm.u1[nbase * 2 + lane] = *reinterpret_cast<uint4*>(p1);
        }
    }
    __syncthreads();

    // ---------------- Phase 2: route b0 (registers), then b1 ---------------
    route_one(sm, u2, tid, lane, wrp, h, coOwn, out + (c * kB + b0) * kCo);

    // reload u2 with b1's priors (same slot addresses, contiguous LDS.128)
    {
        __half2 t[kSlots][4];
        #pragma unroll
        for (int p = 0; p < kSlots; ++p) {
            uint4 w = sm.u1[(p * 192 + wrp * 16) * 2 + lane];
            const __half2* hp = reinterpret_cast<const __half2*>(&w);
            #pragma unroll
            for (int q = 0; q < 4; ++q) t[p][q] = hp[q];
        }
        route_one(sm, t, tid, lane, wrp, h, coOwn, out + (c * kB + b0 + 1) * kCo);
    }
}

extern "C" void kernel_launch(void* const* d_in, const int* in_sizes, int n_in,
                              void* d_out, int out_size)
{
    const float* x = (const float*)d_in[0];
    const float* W = (const float*)d_in[1];
    float* out = (float*)d_out;

    transpose_W_kernel<<<kC * 36, 256>>>(W);

    cudaFuncSetAttribute(caps_routing_kernel,
                         cudaFuncAttributeMaxDynamicSharedMemorySize,
                         (int)sizeof(Smem));
    dim3 grid(kB / kBT, kC);
    caps_routing_kernel<<<grid, kThreads, sizeof(Smem)>>>(x, out);
}